// round 11
// baseline (speedup 1.0000x reference)
#include <cuda_runtime.h>
#include <cuda_fp16.h>
#include <cstdint>

#define BATCH 64
#define N 1024
#define RBLKS 32                      // 32-row blocks per batch
#define NTASK (BATCH * RBLKS)         // 2048 tasks per pass
#define NCTA 444                      // 148 SMs x 3 resident CTAs
#define NTHREAD 256

// Scratch
__device__ float  g_R[BATCH * N];
__device__ float  g_C[BATCH * N];
__device__ __half g_parth[BATCH * RBLKS * N];   // 4 MB half partials
__device__ __half g_e[(size_t)BATCH * N * N];   // 128 MB exp(s) cache
__device__ volatile unsigned g_bar_gen;          // grid barrier generation
__device__ unsigned g_bar_cnt;                   // grid barrier arrivals

// ---------------------------------------------------------------------------
// Grid-wide barrier. Valid because all NCTA CTAs are co-resident
// (__launch_bounds__(256,3) on 148 SMs). gen is monotonic across graph
// replays; cnt self-resets. Uniform call count per CTA -> no deadlock.
// ---------------------------------------------------------------------------
__device__ __forceinline__ void grid_barrier() {
    __syncthreads();                       // CTA writes visible to thread 0
    if (threadIdx.x == 0) {
        const unsigned gen = g_bar_gen;
        __threadfence();                   // cumulative: publish CTA's writes
        const unsigned old = atomicAdd(&g_bar_cnt, 1u);
        if (old == NCTA - 1) {
            g_bar_cnt = 0;
            __threadfence();
            g_bar_gen = gen + 1;
        } else {
            while (g_bar_gen == gen) { __nanosleep(64); }
        }
        __threadfence();
    }
    __syncthreads();
}

// ---------------------------------------------------------------------------
// Pass 0 task (iters 0+1 for one 32-row block of batch b): read fp32 s,
// write half exp cache, R[i] = log(sum_j exp(s_ij)), col partials
// part[j] += exp(s_ij)/sum_i. Warp-per-row, 4 rows per warp.
// ---------------------------------------------------------------------------
__device__ __forceinline__ void pass0_task(const float* __restrict__ s,
                                           int b, int rblk,
                                           __half2 (*stage)[N / 2]) {
    const int tid  = threadIdx.x;
    const int warp = tid >> 5;
    const int lane = tid & 31;

    __half2 cacc[16];
    #pragma unroll
    for (int k = 0; k < 16; k++) cacc[k] = __float2half2_rn(0.f);

    #pragma unroll 1
    for (int g = 0; g < 4; g++) {
        const int row = (rblk << 5) + (g << 3) + warp;
        const float* p  = s   + ((size_t)b << 20) + ((size_t)row << 10);
        __half*      ep = g_e + ((size_t)b << 20) + ((size_t)row << 10);

        __half2 eh[16];
        float sum = 0.f;
        #pragma unroll
        for (int k = 0; k < 8; k++) {
            const int j = (lane << 2) + (k << 7);
            const float4 sv = __ldcs(reinterpret_cast<const float4*>(p + j));
            const float ex = __expf(sv.x), ey = __expf(sv.y);
            const float ez = __expf(sv.z), ew = __expf(sv.w);
            const __half2 h0 = __floats2half2_rn(ex, ey);
            const __half2 h1 = __floats2half2_rn(ez, ew);
            eh[2*k+0] = h0; eh[2*k+1] = h1;
            uint2 u;
            u.x = *reinterpret_cast<const unsigned int*>(&h0);
            u.y = *reinterpret_cast<const unsigned int*>(&h1);
            __stcs(reinterpret_cast<uint2*>(ep + j), u);
            sum += (ex + ey) + (ez + ew);
        }
        #pragma unroll
        for (int off = 16; off; off >>= 1)
            sum += __shfl_xor_sync(0xffffffffu, sum, off);

        if (lane == 0) g_R[b * N + row] = logf(sum);
        const __half2 rin = __float2half2_rn(__fdividef(1.f, sum));
        #pragma unroll
        for (int k = 0; k < 16; k++) cacc[k] = __hfma2(eh[k], rin, cacc[k]);
    }

    #pragma unroll
    for (int k = 0; k < 8; k++) {
        const int jh = (lane << 1) + (k << 6);
        stage[warp][jh]     = cacc[2*k+0];
        stage[warp][jh + 1] = cacc[2*k+1];
    }
    __syncthreads();
    float a0 = 0.f, a1 = 0.f, a2 = 0.f, a3 = 0.f;
    #pragma unroll
    for (int w = 0; w < 8; w++) {
        const float2 f0 = __half22float2(stage[w][(tid << 1)]);
        const float2 f1 = __half22float2(stage[w][(tid << 1) + 1]);
        a0 += f0.x; a1 += f0.y; a2 += f1.x; a3 += f1.y;
    }
    const __half2 h0 = __floats2half2_rn(a0, a1);
    const __half2 h1 = __floats2half2_rn(a2, a3);
    uint2 u;
    u.x = *reinterpret_cast<const unsigned int*>(&h0);
    u.y = *reinterpret_cast<const unsigned int*>(&h1);
    reinterpret_cast<uint2*>(g_parth + ((size_t)(b * RBLKS + rblk)) * N)[tid] = u;
    __syncthreads();   // protect stage for the next task
}

// ---------------------------------------------------------------------------
// Half pass task (one iter pair): reads only the half exp cache.
// exp(s - C) = e * w, w[j] = exp(-C[j]) fp32 in smem.
// ---------------------------------------------------------------------------
__device__ __forceinline__ void passh_task(int b, int rblk,
                                           float* w_s,
                                           __half2 (*stage)[N / 2]) {
    const int tid  = threadIdx.x;
    const int warp = tid >> 5;
    const int lane = tid & 31;

    {   // w = exp(-C[b])
        const float4 c = *reinterpret_cast<const float4*>(&g_C[b * N + (tid << 2)]);
        *reinterpret_cast<float4*>(&w_s[tid << 2]) =
            make_float4(__expf(-c.x), __expf(-c.y), __expf(-c.z), __expf(-c.w));
    }
    __syncthreads();

    __half2 cacc[16];
    #pragma unroll
    for (int k = 0; k < 16; k++) cacc[k] = __float2half2_rn(0.f);

    #pragma unroll 1
    for (int g = 0; g < 4; g++) {
        const int row = (rblk << 5) + (g << 3) + warp;
        const __half* ep = g_e + ((size_t)b << 20) + ((size_t)row << 10);

        __half2 ph[16];
        float sum = 0.f;
        #pragma unroll
        for (int k = 0; k < 4; k++) {
            const int j = (lane << 3) + (k << 8);
            const uint4 u = __ldcs(reinterpret_cast<const uint4*>(ep + j));
            const float2 f0 = __half22float2(*reinterpret_cast<const __half2*>(&u.x));
            const float2 f1 = __half22float2(*reinterpret_cast<const __half2*>(&u.y));
            const float2 f2 = __half22float2(*reinterpret_cast<const __half2*>(&u.z));
            const float2 f3 = __half22float2(*reinterpret_cast<const __half2*>(&u.w));
            const float4 wa = *reinterpret_cast<const float4*>(&w_s[j]);
            const float4 wb = *reinterpret_cast<const float4*>(&w_s[j + 4]);
            const float p0 = f0.x * wa.x, p1 = f0.y * wa.y;
            const float p2 = f1.x * wa.z, p3 = f1.y * wa.w;
            const float p4 = f2.x * wb.x, p5 = f2.y * wb.y;
            const float p6 = f3.x * wb.z, p7 = f3.y * wb.w;
            sum += ((p0 + p1) + (p2 + p3)) + ((p4 + p5) + (p6 + p7));
            ph[4*k+0] = __floats2half2_rn(p0, p1);
            ph[4*k+1] = __floats2half2_rn(p2, p3);
            ph[4*k+2] = __floats2half2_rn(p4, p5);
            ph[4*k+3] = __floats2half2_rn(p6, p7);
        }
        #pragma unroll
        for (int off = 16; off; off >>= 1)
            sum += __shfl_xor_sync(0xffffffffu, sum, off);

        if (lane == 0) g_R[b * N + row] = logf(sum);
        const __half2 rin = __float2half2_rn(__fdividef(1.f, sum));
        #pragma unroll
        for (int k = 0; k < 16; k++) cacc[k] = __hfma2(ph[k], rin, cacc[k]);
    }

    #pragma unroll
    for (int k = 0; k < 4; k++) {
        const int jh = (lane << 2) + (k << 7);
        #pragma unroll
        for (int m = 0; m < 4; m++) stage[warp][jh + m] = cacc[4*k + m];
    }
    __syncthreads();
    float a0 = 0.f, a1 = 0.f, a2 = 0.f, a3 = 0.f;
    #pragma unroll
    for (int w = 0; w < 8; w++) {
        const float2 f0 = __half22float2(stage[w][(tid << 1)]);
        const float2 f1 = __half22float2(stage[w][(tid << 1) + 1]);
        a0 += f0.x; a1 += f0.y; a2 += f1.x; a3 += f1.y;
    }
    const __half2 h0 = __floats2half2_rn(a0, a1);
    const __half2 h1 = __floats2half2_rn(a2, a3);
    uint2 u;
    u.x = *reinterpret_cast<const unsigned int*>(&h0);
    u.y = *reinterpret_cast<const unsigned int*>(&h1);
    reinterpret_cast<uint2*>(g_parth + ((size_t)(b * RBLKS + rblk)) * N)[tid] = u;
    __syncthreads();   // protect stage + w_s for the next task
}

// ---------------------------------------------------------------------------
// Distributed C update: C[b][j] (+)= log(sum_r part[r][j]). First 32768
// threads of the grid each own one half2 column pair.
// ---------------------------------------------------------------------------
__device__ __forceinline__ void c_update(bool first) {
    const int t = blockIdx.x * NTHREAD + threadIdx.x;
    if (t < BATCH * (N / 2)) {
        const int b = t >> 9, jh = t & 511;
        float sx = 0.f, sy = 0.f;
        #pragma unroll
        for (int r = 0; r < RBLKS; r++) {
            const __half2 v = *reinterpret_cast<const __half2*>(
                g_parth + ((size_t)(b * RBLKS + r)) * N + (jh << 1));
            const float2 f = __half22float2(v);
            sx += f.x; sy += f.y;
        }
        float2* c2 = reinterpret_cast<float2*>(&g_C[b * N + (jh << 1)]);
        if (first) {
            *c2 = make_float2(logf(sx), logf(sy));
        } else {
            const float2 c = *c2;
            *c2 = make_float2(logf(sx) + c.x, logf(sy) + c.y);
        }
    }
}

// ---------------------------------------------------------------------------
// Persistent kernel: pass0 | B | C | B | 4x( pass_h | B | C | B ) | out.
// out = e_half * exp(-R[i] - C[j])  (reads the 128 MB cache, not fp32 s).
// ---------------------------------------------------------------------------
__global__ void __launch_bounds__(NTHREAD, 3)
sinkhorn_persist(const float* __restrict__ s, float4* __restrict__ o4) {
    __shared__ float   w_s[N];            // 4 KB
    __shared__ __half2 stage[8][N / 2];   // 16 KB

    #pragma unroll 1
    for (int t = blockIdx.x; t < NTASK; t += NCTA)
        pass0_task(s, t >> 5, t & (RBLKS - 1), stage);
    grid_barrier();
    c_update(true);
    grid_barrier();

    #pragma unroll 1
    for (int p = 0; p < 4; p++) {
        #pragma unroll 1
        for (int t = blockIdx.x; t < NTASK; t += NCTA)
            passh_task(t >> 5, t & (RBLKS - 1), w_s, stage);
        grid_barrier();
        c_update(false);
        grid_barrier();
    }

    // output phase
    const unsigned stride = NCTA * NTHREAD;
    #pragma unroll 1
    for (unsigned gid = blockIdx.x * NTHREAD + threadIdx.x;
         gid < (unsigned)(BATCH * N * N / 4); gid += stride) {
        const size_t base = (size_t)gid << 2;
        const int b = (int)(base >> 20);
        const int i = (int)(base >> 10) & (N - 1);
        const int j = (int)base & (N - 1);
        const uint2 u = __ldcs(reinterpret_cast<const uint2*>(
            g_e + ((size_t)b << 20) + ((size_t)i << 10) + j));
        const float2 e0 = __half22float2(*reinterpret_cast<const __half2*>(&u.x));
        const float2 e1 = __half22float2(*reinterpret_cast<const __half2*>(&u.y));
        const float r = __ldg(&g_R[(b << 10) + i]);
        const float4 c = *reinterpret_cast<const float4*>(&g_C[(b << 10) + j]);
        float4 o;
        o.x = e0.x * __expf(-r - c.x);
        o.y = e0.y * __expf(-r - c.y);
        o.z = e1.x * __expf(-r - c.z);
        o.w = e1.y * __expf(-r - c.w);
        __stcs(o4 + gid, o);
    }
}

// ---------------------------------------------------------------------------
extern "C" void kernel_launch(void* const* d_in, const int* in_sizes, int n_in,
                              void* d_out, int out_size) {
    const float* s = (const float*)d_in[0];
    sinkhorn_persist<<<NCTA, NTHREAD>>>(s, (float4*)d_out);
}

// round 12
// speedup vs baseline: 1.2349x; 1.2349x over previous
#include <cuda_runtime.h>
#include <cuda_fp16.h>
#include <cstdint>

#define BATCH 64
#define N 1024
#define RBLKS 32            // row-blocks per batch (32 rows each)

// Scratch: row offsets R, col offsets C, per-CTA column partials, exp cache
__device__ float  g_R[BATCH * N];
__device__ float  g_C[BATCH * N];
__device__ __half g_parth[BATCH * RBLKS * N];       // 4 MB half partials
__device__ __half g_e[(size_t)BATCH * N * N];       // 128 MB: exp(s) in fp16

// ---------------------------------------------------------------------------
// Pass 0 (iters 0+1): reads fp32 s ONCE, writes e = exp(s) as half for all
// later passes, computes R[i] = log(sum_j exp(s_ij)) and column partials
// part[j] += exp(s_ij)/sum_i. Warp-per-row, 4 rows/warp.
// grid = (RBLKS, BATCH), block = 256.
// ---------------------------------------------------------------------------
__global__ void __launch_bounds__(256) pass0(const float* __restrict__ s) {
    __shared__ __half2 stage[8][N / 2];   // 16 KB
    const int b    = blockIdx.y;
    const int tid  = threadIdx.x;
    const int warp = tid >> 5;
    const int lane = tid & 31;

    __half2 cacc[16];
    #pragma unroll
    for (int k = 0; k < 16; k++) cacc[k] = __float2half2_rn(0.f);

    #pragma unroll 1
    for (int g = 0; g < 4; g++) {
        const int row = (blockIdx.x << 5) + (g << 3) + warp;
        const float*  p  = s   + ((size_t)b << 20) + ((size_t)row << 10);
        __half*       ep = g_e + ((size_t)b << 20) + ((size_t)row << 10);

        __half2 eh[16];
        float sum = 0.f;
        #pragma unroll
        for (int k = 0; k < 8; k++) {
            const int j = (lane << 2) + (k << 7);
            const float4 sv = __ldcs(reinterpret_cast<const float4*>(p + j));
            const float ex = __expf(sv.x), ey = __expf(sv.y);
            const float ez = __expf(sv.z), ew = __expf(sv.w);
            const __half2 h0 = __floats2half2_rn(ex, ey);
            const __half2 h1 = __floats2half2_rn(ez, ew);
            eh[2*k+0] = h0; eh[2*k+1] = h1;
            uint2 u;
            u.x = *reinterpret_cast<const unsigned int*>(&h0);
            u.y = *reinterpret_cast<const unsigned int*>(&h1);
            __stcs(reinterpret_cast<uint2*>(ep + j), u);
            sum += (ex + ey) + (ez + ew);
        }
        #pragma unroll
        for (int off = 16; off; off >>= 1)
            sum += __shfl_xor_sync(0xffffffffu, sum, off);

        if (lane == 0) g_R[b * N + row] = logf(sum);
        const __half2 rin = __float2half2_rn(__fdividef(1.f, sum));
        #pragma unroll
        for (int k = 0; k < 16; k++) cacc[k] = __hfma2(eh[k], rin, cacc[k]);
    }

    #pragma unroll
    for (int k = 0; k < 8; k++) {
        const int jh = (lane << 1) + (k << 6);
        stage[warp][jh]     = cacc[2*k+0];
        stage[warp][jh + 1] = cacc[2*k+1];
    }
    __syncthreads();
    float a0 = 0.f, a1 = 0.f, a2 = 0.f, a3 = 0.f;
    #pragma unroll
    for (int w = 0; w < 8; w++) {
        const float2 f0 = __half22float2(stage[w][(tid << 1)]);
        const float2 f1 = __half22float2(stage[w][(tid << 1) + 1]);
        a0 += f0.x; a1 += f0.y; a2 += f1.x; a3 += f1.y;
    }
    const __half2 h0 = __floats2half2_rn(a0, a1);
    const __half2 h1 = __floats2half2_rn(a2, a3);
    uint2 u;
    u.x = *reinterpret_cast<const unsigned int*>(&h0);
    u.y = *reinterpret_cast<const unsigned int*>(&h1);
    reinterpret_cast<uint2*>(
        g_parth + ((size_t)(b * RBLKS + blockIdx.x)) * N)[tid] = u;
}

// ---------------------------------------------------------------------------
// Half pass (one iter pair), HALF2-NATIVE: reads the 128 MB exp-cache.
// exp(s - C) = e * w with w[j] = exp(-C[j]) computed fp32, STORED half2.
// Per 8 elems: 1 LDG.128 + 1 LDS.128 + 4 HMUL2 + 3 HADD2 + cvt + 2 FADD
// + 4 HFMA2  (~1.8x fewer issue slots than the fp32 version -- the pass is
// issue-bound, not DRAM-bound).
//   row:  sum_i = sum_j e_ij*w_j (pairwise half tree, fp32 across groups)
//   cols: part[j] += e_ij*w_j / sum_i
// grid = (RBLKS, BATCH), block = 256, warp-per-row, 4 rows/warp.
// ---------------------------------------------------------------------------
__global__ void __launch_bounds__(256) pass_h() {
    __shared__ __half2 w2_s[N / 2];       // 1 KB
    __shared__ __half2 stage[8][N / 2];   // 16 KB
    const int b    = blockIdx.y;
    const int tid  = threadIdx.x;
    const int warp = tid >> 5;
    const int lane = tid & 31;

    {   // w = exp(-C[b]) fp32 -> half2
        const float4 c = *reinterpret_cast<const float4*>(&g_C[b * N + (tid << 2)]);
        w2_s[(tid << 1)]     = __floats2half2_rn(__expf(-c.x), __expf(-c.y));
        w2_s[(tid << 1) + 1] = __floats2half2_rn(__expf(-c.z), __expf(-c.w));
    }
    __syncthreads();

    __half2 cacc[16];
    #pragma unroll
    for (int k = 0; k < 16; k++) cacc[k] = __float2half2_rn(0.f);

    #pragma unroll 1
    for (int g = 0; g < 4; g++) {
        const int row = (blockIdx.x << 5) + (g << 3) + warp;
        const __half2* ep2 = reinterpret_cast<const __half2*>(
            g_e + ((size_t)b << 20) + ((size_t)row << 10));

        __half2 ph[16];
        float sum = 0.f;
        #pragma unroll
        for (int k = 0; k < 4; k++) {
            const int jh = (lane << 2) + (k << 7);   // half2 idx; elem j = 2*jh
            const uint4 u  = __ldcs(reinterpret_cast<const uint4*>(ep2 + jh));
            const uint4 wv = *reinterpret_cast<const uint4*>(&w2_s[jh]);
            const __half2 p0 = __hmul2(*reinterpret_cast<const __half2*>(&u.x),
                                       *reinterpret_cast<const __half2*>(&wv.x));
            const __half2 p1 = __hmul2(*reinterpret_cast<const __half2*>(&u.y),
                                       *reinterpret_cast<const __half2*>(&wv.y));
            const __half2 p2 = __hmul2(*reinterpret_cast<const __half2*>(&u.z),
                                       *reinterpret_cast<const __half2*>(&wv.z));
            const __half2 p3 = __hmul2(*reinterpret_cast<const __half2*>(&u.w),
                                       *reinterpret_cast<const __half2*>(&wv.w));
            ph[4*k+0] = p0; ph[4*k+1] = p1; ph[4*k+2] = p2; ph[4*k+3] = p3;
            const __half2 t = __hadd2(__hadd2(p0, p1), __hadd2(p2, p3));
            const float2 tf = __half22float2(t);
            sum += tf.x + tf.y;
        }
        #pragma unroll
        for (int off = 16; off; off >>= 1)
            sum += __shfl_xor_sync(0xffffffffu, sum, off);

        if (lane == 0) g_R[b * N + row] = logf(sum);   // last pass's R -> out
        const __half2 rin = __float2half2_rn(__fdividef(1.f, sum));
        #pragma unroll
        for (int k = 0; k < 16; k++) cacc[k] = __hfma2(ph[k], rin, cacc[k]);
    }

    // cross-warp reduce of column partials (cols j = 2*(lane*4+k*128)+m)
    #pragma unroll
    for (int k = 0; k < 4; k++) {
        const int jh = (lane << 2) + (k << 7);
        #pragma unroll
        for (int m = 0; m < 4; m++) stage[warp][jh + m] = cacc[4*k + m];
    }
    __syncthreads();
    float a0 = 0.f, a1 = 0.f, a2 = 0.f, a3 = 0.f;
    #pragma unroll
    for (int w = 0; w < 8; w++) {
        const float2 f0 = __half22float2(stage[w][(tid << 1)]);
        const float2 f1 = __half22float2(stage[w][(tid << 1) + 1]);
        a0 += f0.x; a1 += f0.y; a2 += f1.x; a3 += f1.y;
    }
    const __half2 h0 = __floats2half2_rn(a0, a1);
    const __half2 h1 = __floats2half2_rn(a2, a3);
    uint2 u;
    u.x = *reinterpret_cast<const unsigned int*>(&h0);
    u.y = *reinterpret_cast<const unsigned int*>(&h1);
    reinterpret_cast<uint2*>(
        g_parth + ((size_t)(b * RBLKS + blockIdx.x)) * N)[tid] = u;
}

// ---------------------------------------------------------------------------
// Finalize: C_new[b][j] = log( sum over RBLKS half partials ) + C_old.
// FIRST=true: the pass ran with C==0 -> write log(sum) directly (must NOT
// read g_C: stale from the previous graph replay). grid = 128 CTAs.
// ---------------------------------------------------------------------------
template <bool FIRST>
__global__ void __launch_bounds__(256) finalize_col() {
    const int q  = blockIdx.x * 256 + threadIdx.x;   // half2 index: b*512 + jh
    const int b  = q >> 9;
    const int jh = q & 511;
    float sx = 0.f, sy = 0.f;
    #pragma unroll
    for (int r = 0; r < RBLKS; r++) {
        const __half2 v = *reinterpret_cast<const __half2*>(
            g_parth + ((size_t)(b * RBLKS + r)) * N + (jh << 1));
        const float2 f = __half22float2(v);
        sx += f.x; sy += f.y;
    }
    float2* c2 = reinterpret_cast<float2*>(&g_C[b * N + (jh << 1)]);
    if (FIRST) {
        *c2 = make_float2(logf(sx), logf(sy));
    } else {
        const float2 c = *c2;
        *c2 = make_float2(logf(sx) + c.x, logf(sy) + c.y);
    }
}

// ---------------------------------------------------------------------------
// Output pass: out = exp(s - R[b][i] - C[b][j]), fp32 s, float4, streaming.
// (Reads fp32 s, not the half cache: keeps output quantization error low.)
// ---------------------------------------------------------------------------
__global__ void __launch_bounds__(256) out_pass(const float4* __restrict__ s4,
                                                float4* __restrict__ o4) {
    const size_t gid  = (size_t)blockIdx.x * 256 + threadIdx.x;
    const size_t base = gid << 2;
    const int b = (int)(base >> 20);
    const int i = (int)(base >> 10) & (N - 1);
    const int j = (int)base & (N - 1);
    const float r = __ldg(&g_R[(b << 10) + i]);
    const float4 c = *reinterpret_cast<const float4*>(&g_C[(b << 10) + j]);
    float4 v = __ldcs(s4 + gid);
    float4 o;
    o.x = __expf(v.x - r - c.x);
    o.y = __expf(v.y - r - c.y);
    o.z = __expf(v.z - r - c.z);
    o.w = __expf(v.w - r - c.w);
    __stcs(o4 + gid, o);
}

// ---------------------------------------------------------------------------
extern "C" void kernel_launch(void* const* d_in, const int* in_sizes, int n_in,
                              void* d_out, int out_size) {
    const float* s = (const float*)d_in[0];
    float* out = (float*)d_out;

    const dim3 fgrid(RBLKS, BATCH);
    const int fin_blocks = BATCH * N / 2 / 256;       // 128
    const int out_blocks = (BATCH * N * N / 4) / 256;

    pass0<<<fgrid, 256>>>(s);                 // iters 0+1, builds exp cache
    finalize_col<true><<<fin_blocks, 256>>>();
    pass_h<<<fgrid, 256>>>();                 // iters 2+3
    finalize_col<false><<<fin_blocks, 256>>>();
    pass_h<<<fgrid, 256>>>();                 // iters 4+5
    finalize_col<false><<<fin_blocks, 256>>>();
    pass_h<<<fgrid, 256>>>();                 // iters 6+7
    finalize_col<false><<<fin_blocks, 256>>>();
    pass_h<<<fgrid, 256>>>();                 // iters 8+9
    finalize_col<false><<<fin_blocks, 256>>>();

    out_pass<<<out_blocks, 256>>>((const float4*)s, (float4*)out);
}

// round 13
// speedup vs baseline: 1.2736x; 1.0314x over previous
#include <cuda_runtime.h>
#include <cuda_fp16.h>
#include <cstdint>

#define BATCH 64
#define N 1024
#define RBLKS 32            // row-blocks per batch (32 rows each)

// Scratch: row offsets R, col offsets C, per-CTA column partials, exp cache
__device__ float  g_R[BATCH * N];
__device__ float  g_C[BATCH * N];
__device__ __half g_parth[BATCH * RBLKS * N];       // 4 MB half partials
__device__ __half g_e[(size_t)BATCH * N * N];       // 128 MB: exp(s) in fp16

// ---------------------------------------------------------------------------
// Pass 0 (iters 0+1): reads fp32 s ONCE, writes e = exp(s) as half for all
// later passes, computes R[i] = log(sum_j exp(s_ij)) and column partials
// part[j] += exp(s_ij)/sum_i. Warp-per-row, 4 rows/warp.
// grid = (RBLKS, BATCH), block = 256.
// ---------------------------------------------------------------------------
__global__ void __launch_bounds__(256) pass0(const float* __restrict__ s) {
    __shared__ __half2 stage[8][N / 2];   // 16 KB
    const int b    = blockIdx.y;
    const int tid  = threadIdx.x;
    const int warp = tid >> 5;
    const int lane = tid & 31;

    __half2 cacc[16];
    #pragma unroll
    for (int k = 0; k < 16; k++) cacc[k] = __float2half2_rn(0.f);

    #pragma unroll 1
    for (int g = 0; g < 4; g++) {
        const int row = (blockIdx.x << 5) + (g << 3) + warp;
        const float*  p  = s   + ((size_t)b << 20) + ((size_t)row << 10);
        __half*       ep = g_e + ((size_t)b << 20) + ((size_t)row << 10);

        __half2 eh[16];
        float sum = 0.f;
        #pragma unroll
        for (int k = 0; k < 8; k++) {
            const int j = (lane << 2) + (k << 7);
            const float4 sv = __ldcs(reinterpret_cast<const float4*>(p + j));
            const float ex = __expf(sv.x), ey = __expf(sv.y);
            const float ez = __expf(sv.z), ew = __expf(sv.w);
            const __half2 h0 = __floats2half2_rn(ex, ey);
            const __half2 h1 = __floats2half2_rn(ez, ew);
            eh[2*k+0] = h0; eh[2*k+1] = h1;
            uint2 u;
            u.x = *reinterpret_cast<const unsigned int*>(&h0);
            u.y = *reinterpret_cast<const unsigned int*>(&h1);
            __stcs(reinterpret_cast<uint2*>(ep + j), u);
            sum += (ex + ey) + (ez + ew);
        }
        #pragma unroll
        for (int off = 16; off; off >>= 1)
            sum += __shfl_xor_sync(0xffffffffu, sum, off);

        if (lane == 0) g_R[b * N + row] = logf(sum);
        const __half2 rin = __float2half2_rn(__fdividef(1.f, sum));
        #pragma unroll
        for (int k = 0; k < 16; k++) cacc[k] = __hfma2(eh[k], rin, cacc[k]);
    }

    #pragma unroll
    for (int k = 0; k < 8; k++) {
        const int jh = (lane << 1) + (k << 6);
        stage[warp][jh]     = cacc[2*k+0];
        stage[warp][jh + 1] = cacc[2*k+1];
    }
    __syncthreads();
    float a0 = 0.f, a1 = 0.f, a2 = 0.f, a3 = 0.f;
    #pragma unroll
    for (int w = 0; w < 8; w++) {
        const float2 f0 = __half22float2(stage[w][(tid << 1)]);
        const float2 f1 = __half22float2(stage[w][(tid << 1) + 1]);
        a0 += f0.x; a1 += f0.y; a2 += f1.x; a3 += f1.y;
    }
    const __half2 h0 = __floats2half2_rn(a0, a1);
    const __half2 h1 = __floats2half2_rn(a2, a3);
    uint2 u;
    u.x = *reinterpret_cast<const unsigned int*>(&h0);
    u.y = *reinterpret_cast<const unsigned int*>(&h1);
    reinterpret_cast<uint2*>(
        g_parth + ((size_t)(b * RBLKS + blockIdx.x)) * N)[tid] = u;
}

// ---------------------------------------------------------------------------
// Half pass (one iter pair), HALF2-NATIVE: reads the 128 MB exp-cache.
// exp(s - C) = e * w with w[j] = exp(-C[j]) computed fp32, STORED half2.
//   row:  sum_i = sum_j e_ij*w_j (pairwise half tree, fp32 across groups)
//   cols: part[j] += e_ij*w_j / sum_i
// grid = (RBLKS, BATCH), block = 256, warp-per-row, 4 rows/warp.
// ---------------------------------------------------------------------------
__global__ void __launch_bounds__(256) pass_h() {
    __shared__ __half2 w2_s[N / 2];       // 1 KB
    __shared__ __half2 stage[8][N / 2];   // 16 KB
    const int b    = blockIdx.y;
    const int tid  = threadIdx.x;
    const int warp = tid >> 5;
    const int lane = tid & 31;

    {   // w = exp(-C[b]) fp32 -> half2
        const float4 c = *reinterpret_cast<const float4*>(&g_C[b * N + (tid << 2)]);
        w2_s[(tid << 1)]     = __floats2half2_rn(__expf(-c.x), __expf(-c.y));
        w2_s[(tid << 1) + 1] = __floats2half2_rn(__expf(-c.z), __expf(-c.w));
    }
    __syncthreads();

    __half2 cacc[16];
    #pragma unroll
    for (int k = 0; k < 16; k++) cacc[k] = __float2half2_rn(0.f);

    #pragma unroll 1
    for (int g = 0; g < 4; g++) {
        const int row = (blockIdx.x << 5) + (g << 3) + warp;
        const __half2* ep2 = reinterpret_cast<const __half2*>(
            g_e + ((size_t)b << 20) + ((size_t)row << 10));

        __half2 ph[16];
        float sum = 0.f;
        #pragma unroll
        for (int k = 0; k < 4; k++) {
            const int jh = (lane << 2) + (k << 7);   // half2 idx; elem j = 2*jh
            const uint4 u  = __ldcs(reinterpret_cast<const uint4*>(ep2 + jh));
            const uint4 wv = *reinterpret_cast<const uint4*>(&w2_s[jh]);
            const __half2 p0 = __hmul2(*reinterpret_cast<const __half2*>(&u.x),
                                       *reinterpret_cast<const __half2*>(&wv.x));
            const __half2 p1 = __hmul2(*reinterpret_cast<const __half2*>(&u.y),
                                       *reinterpret_cast<const __half2*>(&wv.y));
            const __half2 p2 = __hmul2(*reinterpret_cast<const __half2*>(&u.z),
                                       *reinterpret_cast<const __half2*>(&wv.z));
            const __half2 p3 = __hmul2(*reinterpret_cast<const __half2*>(&u.w),
                                       *reinterpret_cast<const __half2*>(&wv.w));
            ph[4*k+0] = p0; ph[4*k+1] = p1; ph[4*k+2] = p2; ph[4*k+3] = p3;
            const __half2 t = __hadd2(__hadd2(p0, p1), __hadd2(p2, p3));
            const float2 tf = __half22float2(t);
            sum += tf.x + tf.y;
        }
        #pragma unroll
        for (int off = 16; off; off >>= 1)
            sum += __shfl_xor_sync(0xffffffffu, sum, off);

        if (lane == 0) g_R[b * N + row] = logf(sum);   // last pass's R -> out
        const __half2 rin = __float2half2_rn(__fdividef(1.f, sum));
        #pragma unroll
        for (int k = 0; k < 16; k++) cacc[k] = __hfma2(ph[k], rin, cacc[k]);
    }

    // cross-warp reduce of column partials (cols j = 2*(lane*4+k*128)+m)
    #pragma unroll
    for (int k = 0; k < 4; k++) {
        const int jh = (lane << 2) + (k << 7);
        #pragma unroll
        for (int m = 0; m < 4; m++) stage[warp][jh + m] = cacc[4*k + m];
    }
    __syncthreads();
    float a0 = 0.f, a1 = 0.f, a2 = 0.f, a3 = 0.f;
    #pragma unroll
    for (int w = 0; w < 8; w++) {
        const float2 f0 = __half22float2(stage[w][(tid << 1)]);
        const float2 f1 = __half22float2(stage[w][(tid << 1) + 1]);
        a0 += f0.x; a1 += f0.y; a2 += f1.x; a3 += f1.y;
    }
    const __half2 h0 = __floats2half2_rn(a0, a1);
    const __half2 h1 = __floats2half2_rn(a2, a3);
    uint2 u;
    u.x = *reinterpret_cast<const unsigned int*>(&h0);
    u.y = *reinterpret_cast<const unsigned int*>(&h1);
    reinterpret_cast<uint2*>(
        g_parth + ((size_t)(b * RBLKS + blockIdx.x)) * N)[tid] = u;
}

// ---------------------------------------------------------------------------
// Finalize: C_new[b][j] = log( sum over RBLKS half partials ) + C_old.
// FIRST=true: the pass ran with C==0 -> write log(sum) directly (must NOT
// read g_C: stale from the previous graph replay). grid = 128 CTAs.
// ---------------------------------------------------------------------------
template <bool FIRST>
__global__ void __launch_bounds__(256) finalize_col() {
    const int q  = blockIdx.x * 256 + threadIdx.x;   // half2 index: b*512 + jh
    const int b  = q >> 9;
    const int jh = q & 511;
    float sx = 0.f, sy = 0.f;
    #pragma unroll
    for (int r = 0; r < RBLKS; r++) {
        const __half2 v = *reinterpret_cast<const __half2*>(
            g_parth + ((size_t)(b * RBLKS + r)) * N + (jh << 1));
        const float2 f = __half22float2(v);
        sx += f.x; sy += f.y;
    }
    float2* c2 = reinterpret_cast<float2*>(&g_C[b * N + (jh << 1)]);
    if (FIRST) {
        *c2 = make_float2(logf(sx), logf(sy));
    } else {
        const float2 c = *c2;
        *c2 = make_float2(logf(sx) + c.x, logf(sy) + c.y);
    }
}

// ---------------------------------------------------------------------------
// Output pass: out = e_half * exp(-R[b][i] - C[b][j]).
// Reads the 128 MB half exp-cache instead of fp32 s: 384 MB total traffic
// instead of 512 MB. 8 elements per thread (one uint4 of half2s).
// ---------------------------------------------------------------------------
__global__ void __launch_bounds__(256) out_pass(float4* __restrict__ o4) {
    const size_t gid  = (size_t)blockIdx.x * 256 + threadIdx.x;
    const size_t base = gid << 3;                    // element index (8/thread)
    const int b = (int)(base >> 20);
    const int i = (int)(base >> 10) & (N - 1);
    const int j = (int)base & (N - 1);

    const uint4 u = __ldcs(reinterpret_cast<const uint4*>(
        g_e + ((size_t)b << 20) + ((size_t)i << 10) + j));
    const float2 e0 = __half22float2(*reinterpret_cast<const __half2*>(&u.x));
    const float2 e1 = __half22float2(*reinterpret_cast<const __half2*>(&u.y));
    const float2 e2 = __half22float2(*reinterpret_cast<const __half2*>(&u.z));
    const float2 e3 = __half22float2(*reinterpret_cast<const __half2*>(&u.w));

    const float r = __ldg(&g_R[(b << 10) + i]);
    const float4 ca = *reinterpret_cast<const float4*>(&g_C[(b << 10) + j]);
    const float4 cb = *reinterpret_cast<const float4*>(&g_C[(b << 10) + j + 4]);

    float4 oa, ob;
    oa.x = e0.x * __expf(-r - ca.x);
    oa.y = e0.y * __expf(-r - ca.y);
    oa.z = e1.x * __expf(-r - ca.z);
    oa.w = e1.y * __expf(-r - ca.w);
    ob.x = e2.x * __expf(-r - cb.x);
    ob.y = e2.y * __expf(-r - cb.y);
    ob.z = e3.x * __expf(-r - cb.z);
    ob.w = e3.y * __expf(-r - cb.w);
    __stcs(o4 + (gid << 1), oa);
    __stcs(o4 + (gid << 1) + 1, ob);
}

// ---------------------------------------------------------------------------
extern "C" void kernel_launch(void* const* d_in, const int* in_sizes, int n_in,
                              void* d_out, int out_size) {
    const float* s = (const float*)d_in[0];
    float* out = (float*)d_out;

    const dim3 fgrid(RBLKS, BATCH);
    const int fin_blocks = BATCH * N / 2 / 256;       // 128
    const int out_blocks = (BATCH * N * N / 8) / 256; // 8 elems per thread

    pass0<<<fgrid, 256>>>(s);                 // iters 0+1, builds exp cache
    finalize_col<true><<<fin_blocks, 256>>>();
    pass_h<<<fgrid, 256>>>();                 // iters 2+3
    finalize_col<false><<<fin_blocks, 256>>>();
    pass_h<<<fgrid, 256>>>();                 // iters 4+5
    finalize_col<false><<<fin_blocks, 256>>>();
    pass_h<<<fgrid, 256>>>();                 // iters 6+7
    finalize_col<false><<<fin_blocks, 256>>>();
    pass_h<<<fgrid, 256>>>();                 // iters 8+9
    finalize_col<false><<<fin_blocks, 256>>>();

    out_pass<<<out_blocks, 256>>>((float4*)out);
}